// round 13
// baseline (speedup 1.0000x reference)
#include <cuda_runtime.h>
#include <cstdint>

#define BB 16
#define NN 25200
#define CC 85
#define NCLS 80
#define MAXDET 300
#define BINS 2048
#define CAP 512
#define SLOTCAP 32
#define CLSCAP 48
#define CONF_T 0.25f
#define IOU_T 0.45f
#define MAXWH 4096.0f
#define NEGF  -1e30f

#define GBOX 192
#define PTHREADS 192
#define TILE_BYTES (GBOX * CC * 4)     // 65280, multiple of 16

typedef unsigned long long u64;

// Global scratch (zero-initialized at load; g_hist reset by k_nms each run)
__device__ float  g_score[BB * NN];
__device__ float4 g_box[BB * NN];
__device__ int    g_cls[BB * NN];
__device__ int    g_hist[BB * BINS];
__device__ u64    g_bucket[BB * BINS * SLOTCAP];

__device__ __forceinline__ int score_bin(float s) {
    int bin = (int)((s - CONF_T) * (BINS / 0.75f));
    return min(max(bin, 0), BINS - 1);
}

// Decide fl(inter/denom) > IOU_T without division (exact vs reference).
__device__ __forceinline__ bool iou_sup(float inter, float denom) {
    float s = fmaf(-IOU_T, denom, inter);
    if (fabsf(s) > 1e-6f * denom) return s > 0.0f;
    return (inter / denom) > IOU_T;
}

__device__ __forceinline__ unsigned smem_addr(const void* p) {
    unsigned a;
    asm("{ .reg .u64 t; cvta.to.shared.u64 t, %1; cvt.u32.u64 %0, t; }"
        : "=r"(a) : "l"(p));
    return a;
}

// TMA-streamed prep (R9 shape): one cp.async.bulk per block, then
// thread-per-box conf/argmax/box + bucket scatter.
// Invalid boxes write NOTHING: g_score is zero-initialized (0 <= CONF_T) and
// replays are deterministic, so skipping the NEGF store is safe.
__global__ __launch_bounds__(PTHREADS) void k_prep(const float* __restrict__ pred) {
    extern __shared__ __align__(128) float sbuf[];
    __shared__ __align__(8) unsigned long long mbar;
    int tid = threadIdx.x;
    const float* src = pred + (long long)blockIdx.x * (GBOX * CC);
    unsigned sb = smem_addr(sbuf);
    unsigned mb = smem_addr(&mbar);

    if (tid == 0)
        asm volatile("mbarrier.init.shared.b64 [%0], %1;" :: "r"(mb), "r"(1) : "memory");
    __syncthreads();
    if (tid == 0) {
        asm volatile("mbarrier.arrive.expect_tx.shared.b64 _, [%0], %1;"
                     :: "r"(mb), "r"((unsigned)TILE_BYTES) : "memory");
        asm volatile("cp.async.bulk.shared::cluster.global.mbarrier::complete_tx::bytes "
                     "[%0], [%1], %2, [%3];"
                     :: "r"(sb), "l"(src), "r"((unsigned)TILE_BYTES), "r"(mb) : "memory");
    }
    {
        unsigned done = 0;
        while (!done) {
            asm volatile(
                "{\n\t.reg .pred p;\n\t"
                "mbarrier.try_wait.parity.acquire.cta.shared::cta.b64 p, [%1], %2, 0x989680;\n\t"
                "selp.b32 %0, 1, 0, p;\n\t}"
                : "=r"(done) : "r"(mb), "r"(0u) : "memory");
        }
    }

    {
        const float* p = sbuf + tid * CC;
        int w = blockIdx.x * GBOX + tid;
        float obj = p[4];
        if (obj <= CONF_T) return;           // valid requires obj > 0.25

        float best = -1.0f;
        int   bj   = 0;
        #pragma unroll 8
        for (int c = 0; c < NCLS; c++) {
            float v = p[5 + c] * obj;            // same op order as reference
            if (v > best) { best = v; bj = c; }  // strict > == first-max argmax
        }
        if (best > CONF_T) {
            g_score[w] = best;
            float x = p[0], y = p[1], ww = p[2], hh = p[3];
            g_box[w] = make_float4(x - ww * 0.5f, y - hh * 0.5f,
                                   x + ww * 0.5f, y + hh * 0.5f);
            g_cls[w] = bj;
            int b = w / NN;
            int n = w - b * NN;
            int cell = b * BINS + score_bin(best);
            int slot = atomicAdd(&g_hist[cell], 1);
            if (slot < SLOTCAP)
                g_bucket[cell * SLOTCAP + slot] =
                    ((u64)__float_as_uint(best) << 32) |
                    (unsigned)~(((unsigned)n << 7) | (unsigned)bj);
        }
    }
}

// Bitonic compare-exchange via shfl_xor (u64 key, descending)
__device__ __forceinline__ u64 cex_shfl(u64 key, int j, int k, int tid) {
    u64 other = __shfl_xor_sync(0xffffffffu, key, j);
    bool lower = (tid & j) == 0;
    bool desc  = (tid & k) == 0;
    bool takemax = (lower == desc);
    bool gt = key > other;
    return (takemax == gt) ? key : other;
}

// smem offsets (bytes)
#define OFF_KEYS   0
#define OFF_CBOX   4096
#define OFF_CAREA  12288
#define OFF_CARRY  14336
#define OFF_CARA   19200
#define OFF_HIST   20416
#define OFF_MSKT   28608
#define OFF_KW     61440
#define OFF_CCLS   61504
#define OFF_BOFF   63552
#define OFF_CLIST  71744
#define OFF_CLCNT  79424
#define SMEM_TOTAL 79744

__global__ __launch_bounds__(1024, 1) void k_nms(float* __restrict__ out, int out_size) {
    extern __shared__ char smem[];
    u64*    keys  = (u64*)   (smem + OFF_KEYS);
    float4* cbox  = (float4*)(smem + OFF_CBOX);
    float*  carea = (float*) (smem + OFF_CAREA);
    float4* carry = (float4*)(smem + OFF_CARRY);
    float*  cara  = (float*) (smem + OFF_CARA);
    int*    hist  = (int*)   (smem + OFF_HIST);
    u64*    mskT  = (u64*)   (smem + OFF_MSKT);
    u64*    kw    = (u64*)   (smem + OFF_KW);
    int*    ccls  = (int*)   (smem + OFF_CCLS);
    int*    boff  = (int*)   (smem + OFF_BOFF);
    unsigned short* clist = (unsigned short*)(smem + OFF_CLIST);
    int*    clcnt = (int*)   (smem + OFF_CLCNT);

    __shared__ int s_T, s_top, s_base, s_len, s_ovf, s_clovf, s_changed;
    __shared__ int s_tstar, s_c0, s_wstart, s_ocnt;
    __shared__ int s_wsum[32];
    __shared__ unsigned s_bal[32];

    int b = blockIdx.x, tid = threadIdx.x;
    const int bs = 1024;
    int lane = tid & 31;
    int wid  = tid >> 5;
    const float*  sc  = g_score + b * NN;
    const float4* bxp = g_box   + b * NN;
    const int*    clp = g_cls   + b * NN;

    for (int i = tid; i < BINS; i += bs) hist[i] = g_hist[b * BINS + i];
    if (tid == 0) { s_top = BINS - 1; s_base = 0; }
    __syncthreads();

    while (true) {
        // ── Windowed threshold selection ──
        if (tid == 0) { s_c0 = 0; s_wstart = s_top; s_T = -1; s_len = 0; s_ovf = 0; s_clovf = 0; }
        __syncthreads();
        while (s_T < 0) {
            int wstart = s_wstart, c0 = s_c0;
            int bin = wstart - tid;
            int val = (bin >= 0) ? hist[bin] : 0;
            int incl = val;
            #pragma unroll
            for (int o = 1; o < 32; o <<= 1) {
                int y = __shfl_up_sync(0xffffffffu, incl, o);
                if (lane >= o) incl += y;
            }
            if (lane == 31) s_wsum[wid] = incl;
            __syncthreads();
            if (wid == 0) {
                int v = s_wsum[lane];
                #pragma unroll
                for (int o = 1; o < 32; o <<= 1) {
                    int y = __shfl_up_sync(0xffffffffu, v, o);
                    if (lane >= o) v += y;
                }
                s_wsum[lane] = v;
            }
            if (tid == 0) s_tstar = 1024;
            __syncthreads();
            if (wid > 0) incl += s_wsum[wid - 1];
            int cumBefore = c0 + incl - val;
            bool brk = (cumBefore > 0) && (c0 + incl > CAP);
            if (brk) atomicMin(&s_tstar, tid);
            __syncthreads();
            int tstar = s_tstar;
            if (tid < tstar && bin >= 0) boff[bin] = cumBefore;
            if (tstar < 1024) {
                if (tstar == 0) { if (tid == 0) { s_T = wstart + 1; s_len = c0; } }
                else if (tid == tstar - 1) { s_T = wstart - tstar + 1; s_len = c0 + incl; }
            } else if (wstart - 1023 <= 0) {
                if (bin == 0) { s_T = 0; s_len = c0 + incl; }
            } else {
                if (tid == 1023) s_c0 = c0 + incl;
                if (tid == 0)    s_wstart = wstart - 1024;
            }
            __syncthreads();
        }
        int T = s_T, top = s_top;
        int len = min(s_len, CAP);

        // ── Zero mask / class counters (before fused bucket phase) ──
        for (int t = tid; t < CAP * 8; t += bs) mskT[t] = 0ULL;
        for (int i = tid; i < NCLS; i += bs) clcnt[i] = 0;
        __syncthreads();

        // ── FUSED: bucket copy + per-bin warp sort + staging + class list ──
        for (int bin = top - wid; bin >= T; bin -= 32) {
            int cnt = hist[bin];
            if (cnt == 0) continue;
            if (cnt > SLOTCAP) { s_ovf = 1; continue; }
            u64 bk = (lane < cnt) ? g_bucket[(b * BINS + bin) * SLOTCAP + lane] : 0ULL;
            #pragma unroll
            for (int kk = 2; kk <= 32; kk <<= 1)
                for (int jj = kk >> 1; jj > 0; jj >>= 1)
                    bk = cex_shfl(bk, jj, kk, lane);
            if (lane < cnt) {
                int pos = boff[bin] + lane;
                if (pos < CAP) {
                    keys[pos] = bk;
                    unsigned packed = ~(unsigned)bk;
                    int idx = (int)(packed >> 7);
                    int cl  = (int)(packed & 127u);
                    float4 bx = bxp[idx];
                    float off = (float)cl * MAXWH;
                    float4 cb = make_float4(bx.x + off, bx.y + off,
                                            bx.z + off, bx.w + off);
                    cbox[pos]  = cb;
                    carea[pos] = (cb.z - cb.x) * (cb.w - cb.y);
                    ccls[pos]  = cl;
                    int slot = atomicAdd(&clcnt[cl], 1);
                    if (slot < CLSCAP) clist[cl * CLSCAP + slot] = (unsigned short)pos;
                    else s_clovf = 1;
                }
            }
        }
        __syncthreads();

        // Rare fallback: bucket overflow -> scan-gather + full bitonic + restage
        if (s_ovf) {
            if (tid == 0) { s_ocnt = 0; s_clovf = 1; }  // force quadratic mask build
            __syncthreads();
            const int NPAD = ((NN + bs - 1) / bs) * bs;
            for (int i = tid; i < NPAD; i += bs) {
                bool take = false;
                float s = NEGF;
                if (i < NN) {
                    s = sc[i];
                    if (s > CONF_T) {
                        int bin = score_bin(s);
                        take = (bin >= T && bin <= top);
                    }
                }
                unsigned bal = __ballot_sync(0xffffffffu, take);
                if (bal) {
                    int base;
                    if (lane == 0) base = atomicAdd(&s_ocnt, __popc(bal));
                    base = __shfl_sync(0xffffffffu, base, 0);
                    if (take) {
                        int pos = base + __popc(bal & ((1u << lane) - 1u));
                        if (pos < CAP)
                            keys[pos] = ((u64)__float_as_uint(s) << 32) |
                                        (unsigned)~(((unsigned)i << 7) |
                                                    (unsigned)clp[i]);
                    }
                }
            }
            __syncthreads();
            if (tid < CAP - len) keys[len + tid] = 0ULL;
            __syncthreads();
            for (int kk = 2; kk <= CAP; kk <<= 1) {
                for (int jj = kk >> 1; jj > 0; jj >>= 1) {
                    if (tid < CAP) {
                        int i = tid, ixj = i ^ jj;
                        if (ixj > i) {
                            u64 a = keys[i], c2 = keys[ixj];
                            bool sw = ((i & kk) == 0) ? (a < c2) : (a > c2);
                            if (sw) { keys[i] = c2; keys[ixj] = a; }
                        }
                    }
                    __syncthreads();
                }
            }
            // restage payloads from sorted keys
            if (tid < len) {
                u64 bk = keys[tid];
                unsigned packed = ~(unsigned)bk;
                int idx = (int)(packed >> 7);
                int cl  = (int)(packed & 127u);
                float4 bx = bxp[idx];
                float off = (float)cl * MAXWH;
                float4 cb = make_float4(bx.x + off, bx.y + off, bx.z + off, bx.w + off);
                cbox[tid]  = cb;
                carea[tid] = (cb.z - cb.x) * (cb.w - cb.y);
                ccls[tid]  = cl;
            }
            __syncthreads();
        }

        // ── Decode + carry pre-suppression (register) + mask build ──
        u64 key = 0; int myidx = 0, mycls = 0;
        bool presb = false;
        if (tid < len) {
            key = keys[tid];
            unsigned packed = ~(unsigned)key;
            myidx = (int)(packed >> 7);
            mycls = (int)(packed & 127u);
            float4 bi = cbox[tid];
            float  ai = carea[tid];
            if (s_base > 0) {
                for (int q = 0; q < s_base && !presb; q++) {
                    float4 kb = carry[q];
                    float xx1 = fmaxf(bi.x, kb.x), yy1 = fmaxf(bi.y, kb.y);
                    float xx2 = fminf(bi.z, kb.z), yy2 = fminf(bi.w, kb.w);
                    float inter = fmaxf(xx2 - xx1, 0.0f) * fmaxf(yy2 - yy1, 0.0f);
                    if (inter > 0.0f)
                        presb = iou_sup(inter, ai + cara[q] - inter);
                }
            }
            if (!s_clovf) {
                int cnt = clcnt[mycls];
                for (int q = 0; q < cnt; q++) {
                    int j = clist[mycls * CLSCAP + q];
                    if (j < tid) {
                        float4 bj = cbox[j];
                        float xx1 = fmaxf(bi.x, bj.x), yy1 = fmaxf(bi.y, bj.y);
                        float xx2 = fminf(bi.z, bj.z), yy2 = fminf(bi.w, bj.w);
                        float inter = fmaxf(xx2 - xx1, 0.0f) * fmaxf(yy2 - yy1, 0.0f);
                        if (inter > 0.0f && iou_sup(inter, ai + carea[j] - inter))
                            mskT[tid * 8 + (j >> 6)] |= 1ULL << (j & 63);
                    }
                }
            }
        }
        if (s_clovf) {
            // quadratic column-major build (no class lists needed)
            for (int t = tid; t < CAP * 8; t += bs) {
                int c = t >> 3, w = t & 7;
                u64 mword = 0ULL;
                if (c < len) {
                    float4 bi = cbox[c];
                    float  ai = carea[c];
                    int ci = ccls[c];
                    int jbeg = w << 6;
                    int jend = min(jbeg + 64, c);
                    for (int j = jbeg; j < jend; j++) {
                        if (ccls[j] != ci) continue;
                        float4 bj = cbox[j];
                        float xx1 = fmaxf(bi.x, bj.x), yy1 = fmaxf(bi.y, bj.y);
                        float xx2 = fminf(bi.z, bj.z), yy2 = fminf(bi.w, bj.w);
                        float inter = fmaxf(xx2 - xx1, 0.0f) * fmaxf(yy2 - yy1, 0.0f);
                        if (inter > 0.0f && iou_sup(inter, ai + carea[j] - inter))
                            mword |= 1ULL << (j & 63);
                    }
                }
                mskT[t] = mword;
            }
        }
        __syncthreads();

        // ── Exact greedy via antitone fixpoint iteration ──
        bool keptf = (tid < len) && !presb;
        unsigned balv = __ballot_sync(0xffffffffu, keptf);
        if (lane == 0) s_bal[wid] = balv;
        if (tid == 0) s_changed = 0;
        __syncthreads();
        if (tid < 8) kw[tid] = (u64)s_bal[2 * tid] | ((u64)s_bal[2 * tid + 1] << 32);
        __syncthreads();
        for (int pass = 0; pass <= CAP; pass++) {
            bool sup = false;
            if (tid < len) {
                const u64* row = mskT + tid * 8;
                u64 acc = 0ULL;
                #pragma unroll
                for (int w = 0; w < 8; w++) acc |= kw[w] & row[w];
                sup = acc != 0ULL;
            }
            bool nk = (tid < len) && !presb && !sup;
            __syncthreads();
            unsigned nb = __ballot_sync(0xffffffffu, nk);
            if (lane == 0) s_bal[wid] = nb;
            __syncthreads();
            if (tid < 8) {
                u64 nw = (u64)s_bal[2 * tid] | ((u64)s_bal[2 * tid + 1] << 32);
                if (nw != kw[tid]) s_changed = 1;
                kw[tid] = nw;
            }
            __syncthreads();
            if (!s_changed) break;
            if (tid == 0) s_changed = 0;
            __syncthreads();
        }

        // ── Compaction + ordered output ──
        int flag = 0, ex = 0;
        if (tid < CAP) {
            bool kept = (kw[tid >> 6] >> (tid & 63)) & 1ULL;
            flag = (tid < len && kept) ? 1 : 0;
            unsigned bal = __ballot_sync(0xffffffffu, flag);
            ex = __popc(bal & ((1u << lane) - 1u));
            if (lane == 0) s_wsum[wid] = __popc(bal);
        }
        __syncthreads();
        if (tid < 16) {
            int v = s_wsum[tid];
            #pragma unroll
            for (int o = 1; o < 16; o <<= 1) {
                int y = __shfl_up_sync(0x0000ffffu, v, o);
                if (tid >= o) v += y;
            }
            s_wsum[tid] = v;
        }
        __syncthreads();
        int total = s_wsum[15];
        int basep = s_base;
        bool cont = (basep + total < MAXDET) && (s_T > 0);

        if (tid < CAP && flag) {
            int warpbase = (tid >= 32) ? s_wsum[wid - 1] : 0;
            int pos = basep + warpbase + ex;
            if (pos < MAXDET) {
                float4 bx = bxp[myidx];
                int base = b * MAXDET * 6 + pos * 6;
                if (base + 5 < out_size) {
                    out[base + 0] = bx.x;
                    out[base + 1] = bx.y;
                    out[base + 2] = bx.z;
                    out[base + 3] = bx.w;
                    out[base + 4] = __uint_as_float((unsigned)(key >> 32));
                    out[base + 5] = (float)mycls;
                }
                int ko = BB * MAXDET * 6 + b * MAXDET + pos;
                if (ko < out_size) out[ko] = 1.0f;
                if (cont) { carry[pos] = cbox[tid]; cara[pos] = carea[tid]; }
            }
        }
        __syncthreads();
        if (tid == 0) { s_base = basep + total; s_top = s_T - 1; }
        __syncthreads();
        if (!cont) break;
    }

    // Zero-pad remaining rows + keeps
    int fin = min(s_base, MAXDET);
    for (int k2 = fin + tid; k2 < MAXDET; k2 += bs) {
        int base = b * MAXDET * 6 + k2 * 6;
        #pragma unroll
        for (int c2 = 0; c2 < 6; c2++)
            if (base + c2 < out_size) out[base + c2] = 0.0f;
        int ko = BB * MAXDET * 6 + b * MAXDET + k2;
        if (ko < out_size) out[ko] = 0.0f;
    }

    // Reset histogram for next graph replay
    for (int i = tid; i < BINS; i += bs) g_hist[b * BINS + i] = 0;
}

extern "C" void kernel_launch(void* const* d_in, const int* in_sizes, int n_in,
                              void* d_out, int out_size) {
    const float* pred = (const float*)d_in[0];
    float* out = (float*)d_out;

    cudaFuncSetAttribute(k_prep, cudaFuncAttributeMaxDynamicSharedMemorySize, TILE_BYTES);
    int blocks = (BB * NN) / GBOX;   // 2100
    k_prep<<<blocks, PTHREADS, TILE_BYTES>>>(pred);

    cudaFuncSetAttribute(k_nms, cudaFuncAttributeMaxDynamicSharedMemorySize, SMEM_TOTAL);
    k_nms<<<BB, 1024, SMEM_TOTAL>>>(out, out_size);
}

// round 14
// speedup vs baseline: 1.0322x; 1.0322x over previous
#include <cuda_runtime.h>
#include <cstdint>

#define BB 16
#define NN 25200
#define CC 85
#define NCLS 80
#define MAXDET 300
#define BINS 2048
#define CAP 512
#define SLOTCAP 32
#define CLSCAP 48
#define CONF_T 0.25f
#define IOU_T 0.45f
#define MAXWH 4096.0f
#define NEGF  -1e30f

#define GBOX 192
#define PTHREADS 192
#define TILE_BYTES (GBOX * CC * 4)     // 65280, multiple of 16

typedef unsigned long long u64;

// Global scratch (zero-initialized at load; g_hist reset by k_nms each run)
__device__ float  g_score[BB * NN];
__device__ float4 g_box[BB * NN];
__device__ int    g_cls[BB * NN];
__device__ int    g_hist[BB * BINS];
__device__ u64    g_bucket[BB * BINS * SLOTCAP];

__device__ __forceinline__ int score_bin(float s) {
    int bin = (int)((s - CONF_T) * (BINS / 0.75f));
    return min(max(bin, 0), BINS - 1);
}

// Decide fl(inter/denom) > IOU_T without division (exact vs reference).
__device__ __forceinline__ bool iou_sup(float inter, float denom) {
    float s = fmaf(-IOU_T, denom, inter);
    if (fabsf(s) > 1e-6f * denom) return s > 0.0f;
    return (inter / denom) > IOU_T;
}

__device__ __forceinline__ unsigned smem_addr(const void* p) {
    unsigned a;
    asm("{ .reg .u64 t; cvta.to.shared.u64 t, %1; cvt.u32.u64 %0, t; }"
        : "=r"(a) : "l"(p));
    return a;
}

// TMA-streamed prep: one cp.async.bulk per block (contiguous 65280B tile),
// then thread-per-box conf/argmax/box + bucket scatter.  (R9-identical.)
__global__ __launch_bounds__(PTHREADS) void k_prep(const float* __restrict__ pred) {
    extern __shared__ __align__(128) float sbuf[];
    __shared__ __align__(8) unsigned long long mbar;
    int tid = threadIdx.x;
    const float* src = pred + (long long)blockIdx.x * (GBOX * CC);
    unsigned sb = smem_addr(sbuf);
    unsigned mb = smem_addr(&mbar);

    if (tid == 0)
        asm volatile("mbarrier.init.shared.b64 [%0], %1;" :: "r"(mb), "r"(1) : "memory");
    __syncthreads();
    if (tid == 0) {
        asm volatile("mbarrier.arrive.expect_tx.shared.b64 _, [%0], %1;"
                     :: "r"(mb), "r"((unsigned)TILE_BYTES) : "memory");
        asm volatile("cp.async.bulk.shared::cluster.global.mbarrier::complete_tx::bytes "
                     "[%0], [%1], %2, [%3];"
                     :: "r"(sb), "l"(src), "r"((unsigned)TILE_BYTES), "r"(mb) : "memory");
    }
    {
        unsigned done = 0;
        while (!done) {
            asm volatile(
                "{\n\t.reg .pred p;\n\t"
                "mbarrier.try_wait.parity.acquire.cta.shared::cta.b64 p, [%1], %2, 0x989680;\n\t"
                "selp.b32 %0, 1, 0, p;\n\t}"
                : "=r"(done) : "r"(mb), "r"(0u) : "memory");
        }
    }

    {
        const float* p = sbuf + tid * CC;
        int w = blockIdx.x * GBOX + tid;
        float obj = p[4];
        if (obj <= CONF_T) { g_score[w] = NEGF; return; }

        float best = -1.0f;
        int   bj   = 0;
        #pragma unroll 8
        for (int c = 0; c < NCLS; c++) {
            float v = p[5 + c] * obj;            // same op order as reference
            if (v > best) { best = v; bj = c; }  // strict > == first-max argmax
        }
        bool valid = best > CONF_T;
        g_score[w] = valid ? best : NEGF;
        if (valid) {
            float x = p[0], y = p[1], ww = p[2], hh = p[3];
            g_box[w] = make_float4(x - ww * 0.5f, y - hh * 0.5f,
                                   x + ww * 0.5f, y + hh * 0.5f);
            g_cls[w] = bj;
            int b = w / NN;
            int n = w - b * NN;
            int cell = b * BINS + score_bin(best);
            int slot = atomicAdd(&g_hist[cell], 1);
            if (slot < SLOTCAP)
                g_bucket[cell * SLOTCAP + slot] =
                    ((u64)__float_as_uint(best) << 32) |
                    (unsigned)~(((unsigned)n << 7) | (unsigned)bj);
        }
    }
}

// Bitonic compare-exchange via shfl_xor (u64 key, descending)
__device__ __forceinline__ u64 cex_shfl(u64 key, int j, int k, int tid) {
    u64 other = __shfl_xor_sync(0xffffffffu, key, j);
    bool lower = (tid & j) == 0;
    bool desc  = (tid & k) == 0;
    bool takemax = (lower == desc);
    bool gt = key > other;
    return (takemax == gt) ? key : other;
}

// smem offsets (bytes)
#define OFF_KEYS   0
#define OFF_CBOX   4096
#define OFF_CAREA  12288
#define OFF_CARRY  14336
#define OFF_CARA   19200
#define OFF_HIST   20416
#define OFF_MSKT   28608
#define OFF_PRES   61376
#define OFF_KW     61440
#define OFF_CCLS   61504
#define OFF_BOFF   63552
#define OFF_CLIST  71744
#define OFF_CLCNT  79424
#define SMEM_TOTAL 79744

__global__ __launch_bounds__(1024, 1) void k_nms(float* __restrict__ out, int out_size) {
    extern __shared__ char smem[];
    u64*    keys  = (u64*)   (smem + OFF_KEYS);
    float4* cbox  = (float4*)(smem + OFF_CBOX);
    float*  carea = (float*) (smem + OFF_CAREA);
    float4* carry = (float4*)(smem + OFF_CARRY);
    float*  cara  = (float*) (smem + OFF_CARA);
    int*    hist  = (int*)   (smem + OFF_HIST);
    u64*    mskT  = (u64*)   (smem + OFF_MSKT);
    u64*    presw = (u64*)   (smem + OFF_PRES);
    u64*    kw    = (u64*)   (smem + OFF_KW);
    int*    ccls  = (int*)   (smem + OFF_CCLS);
    int*    boff  = (int*)   (smem + OFF_BOFF);
    unsigned short* clist = (unsigned short*)(smem + OFF_CLIST);
    int*    clcnt = (int*)   (smem + OFF_CLCNT);

    __shared__ int s_T, s_top, s_base, s_len, s_ovf, s_clovf, s_changed;
    __shared__ int s_tstar, s_c0, s_wstart, s_ocnt;
    __shared__ int s_wsum[32];
    __shared__ unsigned s_bal[32];

    int b = blockIdx.x, tid = threadIdx.x;
    const int bs = 1024;
    int lane = tid & 31;
    int wid  = tid >> 5;
    const float*  sc  = g_score + b * NN;
    const float4* bxp = g_box   + b * NN;
    const int*    clp = g_cls   + b * NN;

    // PDL: this kernel's blocks may launch before k_prep completes; block
    // here until the primary (k_prep) has finished, before any dependent read.
#if __CUDA_ARCH__ >= 900
    cudaGridDependencySynchronize();
#endif

    for (int i = tid; i < BINS; i += bs) hist[i] = g_hist[b * BINS + i];
    if (tid == 0) { s_top = BINS - 1; s_base = 0; }
    __syncthreads();

    while (true) {
        // ── Windowed threshold selection ──
        if (tid == 0) { s_c0 = 0; s_wstart = s_top; s_T = -1; s_len = 0; s_ovf = 0; }
        __syncthreads();
        while (s_T < 0) {
            int wstart = s_wstart, c0 = s_c0;
            int bin = wstart - tid;
            int val = (bin >= 0) ? hist[bin] : 0;
            int incl = val;
            #pragma unroll
            for (int o = 1; o < 32; o <<= 1) {
                int y = __shfl_up_sync(0xffffffffu, incl, o);
                if (lane >= o) incl += y;
            }
            if (lane == 31) s_wsum[wid] = incl;
            __syncthreads();
            if (wid == 0) {
                int v = s_wsum[lane];
                #pragma unroll
                for (int o = 1; o < 32; o <<= 1) {
                    int y = __shfl_up_sync(0xffffffffu, v, o);
                    if (lane >= o) v += y;
                }
                s_wsum[lane] = v;
            }
            if (tid == 0) s_tstar = 1024;
            __syncthreads();
            if (wid > 0) incl += s_wsum[wid - 1];
            int cumBefore = c0 + incl - val;
            bool brk = (cumBefore > 0) && (c0 + incl > CAP);
            if (brk) atomicMin(&s_tstar, tid);
            __syncthreads();
            int tstar = s_tstar;
            if (tid < tstar && bin >= 0) boff[bin] = cumBefore;
            if (tstar < 1024) {
                if (tstar == 0) { if (tid == 0) { s_T = wstart + 1; s_len = c0; } }
                else if (tid == tstar - 1) { s_T = wstart - tstar + 1; s_len = c0 + incl; }
            } else if (wstart - 1023 <= 0) {
                if (bin == 0) { s_T = 0; s_len = c0 + incl; }
            } else {
                if (tid == 1023) s_c0 = c0 + incl;
                if (tid == 0)    s_wstart = wstart - 1024;
            }
            __syncthreads();
        }
        int T = s_T, top = s_top;
        int len = min(s_len, CAP);

        // ── Bucket copy + per-bin warp sort (global order = desc bins) ──
        for (int bin = top - wid; bin >= T; bin -= 32) {
            int cnt = hist[bin];
            if (cnt == 0) continue;
            if (cnt > SLOTCAP) { s_ovf = 1; continue; }
            u64 bk = (lane < cnt) ? g_bucket[(b * BINS + bin) * SLOTCAP + lane] : 0ULL;
            #pragma unroll
            for (int kk = 2; kk <= 32; kk <<= 1)
                for (int jj = kk >> 1; jj > 0; jj >>= 1)
                    bk = cex_shfl(bk, jj, kk, lane);
            if (lane < cnt) {
                int pos = boff[bin] + lane;
                if (pos < CAP) keys[pos] = bk;
            }
        }
        __syncthreads();

        // Rare fallback: bucket overflow -> scan-gather + full smem bitonic
        if (s_ovf) {
            if (tid == 0) s_ocnt = 0;
            __syncthreads();
            const int NPAD = ((NN + bs - 1) / bs) * bs;
            for (int i = tid; i < NPAD; i += bs) {
                bool take = false;
                float s = NEGF;
                if (i < NN) {
                    s = sc[i];
                    if (s > CONF_T) {
                        int bin = score_bin(s);
                        take = (bin >= T && bin <= top);
                    }
                }
                unsigned bal = __ballot_sync(0xffffffffu, take);
                if (bal) {
                    int base;
                    if (lane == 0) base = atomicAdd(&s_ocnt, __popc(bal));
                    base = __shfl_sync(0xffffffffu, base, 0);
                    if (take) {
                        int pos = base + __popc(bal & ((1u << lane) - 1u));
                        if (pos < CAP)
                            keys[pos] = ((u64)__float_as_uint(s) << 32) |
                                        (unsigned)~(((unsigned)i << 7) |
                                                    (unsigned)clp[i]);
                    }
                }
            }
            __syncthreads();
            if (tid < CAP - len) keys[len + tid] = 0ULL;
            __syncthreads();
            for (int kk = 2; kk <= CAP; kk <<= 1) {
                for (int jj = kk >> 1; jj > 0; jj >>= 1) {
                    if (tid < CAP) {
                        int i = tid, ixj = i ^ jj;
                        if (ixj > i) {
                            u64 a = keys[i], c2 = keys[ixj];
                            bool sw = ((i & kk) == 0) ? (a < c2) : (a > c2);
                            if (sw) { keys[i] = c2; keys[ixj] = a; }
                        }
                    }
                    __syncthreads();
                }
            }
        }

        // ── Stage payloads ──
        u64 key = 0; int myidx = 0, mycls = 0;
        if (tid < len) {
            key = keys[tid];
            unsigned packed = ~(unsigned)key;
            myidx = (int)(packed >> 7);
            mycls = (int)(packed & 127u);
            float4 bx = bxp[myidx];
            float off = (float)mycls * MAXWH;
            float4 cb = make_float4(bx.x + off, bx.y + off, bx.z + off, bx.w + off);
            cbox[tid]  = cb;
            carea[tid] = (cb.z - cb.x) * (cb.w - cb.y);
            ccls[tid]  = mycls;
        }
        for (int t = tid; t < CAP * 8; t += bs) mskT[t] = 0ULL;
        if (tid < 8) presw[tid] = 0ULL;
        for (int i = tid; i < NCLS; i += bs) clcnt[i] = 0;
        if (tid == 0) s_clovf = 0;
        __syncthreads();

        if (tid < len) {
            int slot = atomicAdd(&clcnt[mycls], 1);
            if (slot < CLSCAP) clist[mycls * CLSCAP + slot] = (unsigned short)tid;
            else s_clovf = 1;
        }

        if (s_base > 0 && tid < len) {
            float4 bi = cbox[tid];
            float  ai = carea[tid];
            bool sup = false;
            for (int q = 0; q < s_base && !sup; q++) {
                float4 kb = carry[q];
                float xx1 = fmaxf(bi.x, kb.x), yy1 = fmaxf(bi.y, kb.y);
                float xx2 = fminf(bi.z, kb.z), yy2 = fminf(bi.w, kb.w);
                float inter = fmaxf(xx2 - xx1, 0.0f) * fmaxf(yy2 - yy1, 0.0f);
                if (inter > 0.0f)
                    sup = iou_sup(inter, ai + cara[q] - inter);
            }
            if (sup) atomicOr(&presw[tid >> 6], 1ULL << (tid & 63));
        }
        __syncthreads();

        // ── Column-major suppression mask via class lists ──
        if (!s_clovf) {
            if (tid < len) {
                int c = tid;
                float4 bi = cbox[c];
                float  ai = carea[c];
                int cnt = clcnt[mycls];
                for (int q = 0; q < cnt; q++) {
                    int j = clist[mycls * CLSCAP + q];
                    if (j < c) {
                        float4 bj = cbox[j];
                        float xx1 = fmaxf(bi.x, bj.x), yy1 = fmaxf(bi.y, bj.y);
                        float xx2 = fminf(bi.z, bj.z), yy2 = fminf(bi.w, bj.w);
                        float inter = fmaxf(xx2 - xx1, 0.0f) * fmaxf(yy2 - yy1, 0.0f);
                        if (inter > 0.0f && iou_sup(inter, ai + carea[j] - inter))
                            mskT[c * 8 + (j >> 6)] |= 1ULL << (j & 63);
                    }
                }
            }
        } else {
            for (int t = tid; t < CAP * 8; t += bs) {
                int c = t >> 3, w = t & 7;
                u64 mword = 0ULL;
                if (c < len) {
                    float4 bi = cbox[c];
                    float  ai = carea[c];
                    int ci = ccls[c];
                    int jbeg = w << 6;
                    int jend = min(jbeg + 64, c);
                    for (int j = jbeg; j < jend; j++) {
                        if (ccls[j] != ci) continue;
                        float4 bj = cbox[j];
                        float xx1 = fmaxf(bi.x, bj.x), yy1 = fmaxf(bi.y, bj.y);
                        float xx2 = fminf(bi.z, bj.z), yy2 = fminf(bi.w, bj.w);
                        float inter = fmaxf(xx2 - xx1, 0.0f) * fmaxf(yy2 - yy1, 0.0f);
                        if (inter > 0.0f && iou_sup(inter, ai + carea[j] - inter))
                            mword |= 1ULL << (j & 63);
                    }
                }
                mskT[t] = mword;
            }
        }
        __syncthreads();

        // ── Exact greedy via antitone fixpoint iteration ──
        bool presb = false;
        if (tid < CAP) presb = (presw[tid >> 6] >> (tid & 63)) & 1ULL;
        bool keptf = (tid < len) && !presb;
        unsigned balv = __ballot_sync(0xffffffffu, keptf);
        if (lane == 0) s_bal[wid] = balv;
        if (tid == 0) s_changed = 0;
        __syncthreads();
        if (tid < 8) kw[tid] = (u64)s_bal[2 * tid] | ((u64)s_bal[2 * tid + 1] << 32);
        __syncthreads();
        for (int pass = 0; pass <= CAP; pass++) {
            bool sup = false;
            if (tid < len) {
                const u64* row = mskT + tid * 8;
                u64 acc = 0ULL;
                #pragma unroll
                for (int w = 0; w < 8; w++) acc |= kw[w] & row[w];
                sup = acc != 0ULL;
            }
            bool nk = (tid < len) && !presb && !sup;
            __syncthreads();
            unsigned nb = __ballot_sync(0xffffffffu, nk);
            if (lane == 0) s_bal[wid] = nb;
            __syncthreads();
            if (tid < 8) {
                u64 nw = (u64)s_bal[2 * tid] | ((u64)s_bal[2 * tid + 1] << 32);
                if (nw != kw[tid]) s_changed = 1;
                kw[tid] = nw;
            }
            __syncthreads();
            if (!s_changed) break;
            if (tid == 0) s_changed = 0;
            __syncthreads();
        }

        // ── Compaction + ordered output ──
        int flag = 0, ex = 0;
        if (tid < CAP) {
            bool kept = (kw[tid >> 6] >> (tid & 63)) & 1ULL;
            flag = (tid < len && kept) ? 1 : 0;
            unsigned bal = __ballot_sync(0xffffffffu, flag);
            ex = __popc(bal & ((1u << lane) - 1u));
            if (lane == 0) s_wsum[wid] = __popc(bal);
        }
        __syncthreads();
        if (tid < 16) {
            int v = s_wsum[tid];
            #pragma unroll
            for (int o = 1; o < 16; o <<= 1) {
                int y = __shfl_up_sync(0x0000ffffu, v, o);
                if (tid >= o) v += y;
            }
            s_wsum[tid] = v;
        }
        __syncthreads();
        int total = s_wsum[15];
        int basep = s_base;
        bool cont = (basep + total < MAXDET) && (s_T > 0);

        if (tid < CAP && flag) {
            int warpbase = (tid >= 32) ? s_wsum[wid - 1] : 0;
            int pos = basep + warpbase + ex;
            if (pos < MAXDET) {
                float4 bx = bxp[myidx];
                int base = b * MAXDET * 6 + pos * 6;
                if (base + 5 < out_size) {
                    out[base + 0] = bx.x;
                    out[base + 1] = bx.y;
                    out[base + 2] = bx.z;
                    out[base + 3] = bx.w;
                    out[base + 4] = __uint_as_float((unsigned)(key >> 32));
                    out[base + 5] = (float)mycls;
                }
                int ko = BB * MAXDET * 6 + b * MAXDET + pos;
                if (ko < out_size) out[ko] = 1.0f;
                if (cont) { carry[pos] = cbox[tid]; cara[pos] = carea[tid]; }
            }
        }
        __syncthreads();
        if (tid == 0) { s_base = basep + total; s_top = s_T - 1; }
        __syncthreads();
        if (!cont) break;
    }

    // Zero-pad remaining rows + keeps
    int fin = min(s_base, MAXDET);
    for (int k2 = fin + tid; k2 < MAXDET; k2 += bs) {
        int base = b * MAXDET * 6 + k2 * 6;
        #pragma unroll
        for (int c2 = 0; c2 < 6; c2++)
            if (base + c2 < out_size) out[base + c2] = 0.0f;
        int ko = BB * MAXDET * 6 + b * MAXDET + k2;
        if (ko < out_size) out[ko] = 0.0f;
    }

    // Reset histogram for next graph replay
    for (int i = tid; i < BINS; i += bs) g_hist[b * BINS + i] = 0;
}

extern "C" void kernel_launch(void* const* d_in, const int* in_sizes, int n_in,
                              void* d_out, int out_size) {
    const float* pred = (const float*)d_in[0];
    float* out = (float*)d_out;

    cudaFuncSetAttribute(k_prep, cudaFuncAttributeMaxDynamicSharedMemorySize, TILE_BYTES);
    int blocks = (BB * NN) / GBOX;   // 2100
    k_prep<<<blocks, PTHREADS, TILE_BYTES>>>(pred);

    cudaFuncSetAttribute(k_nms, cudaFuncAttributeMaxDynamicSharedMemorySize, SMEM_TOTAL);

    // PDL launch: k_nms blocks may be dispatched while k_prep drains; the
    // device-side cudaGridDependencySynchronize() enforces the data dependency.
    cudaLaunchConfig_t cfg = {};
    cfg.gridDim = dim3(BB, 1, 1);
    cfg.blockDim = dim3(1024, 1, 1);
    cfg.dynamicSmemBytes = SMEM_TOTAL;
    cfg.stream = 0;
    cudaLaunchAttribute attrs[1];
    attrs[0].id = cudaLaunchAttributeProgrammaticStreamSerialization;
    attrs[0].val.programmaticStreamSerializationAllowed = 1;
    cfg.attrs = attrs;
    cfg.numAttrs = 1;
    cudaError_t err = cudaLaunchKernelEx(&cfg, k_nms, out, out_size);
    if (err != cudaSuccess) {
        // Fallback: plain launch (still correct, just no overlap)
        k_nms<<<BB, 1024, SMEM_TOTAL>>>(out, out_size);
    }
}

// round 15
// speedup vs baseline: 1.0925x; 1.0584x over previous
#include <cuda_runtime.h>
#include <cstdint>

#define BB 16
#define NN 25200
#define CC 85
#define NCLS 80
#define MAXDET 300
#define BINS 2048
#define CAP 384
#define CWORDS 6
#define SORTN 512
#define SLOTCAP 32
#define CLSCAP 48
#define CONF_T 0.25f
#define IOU_T 0.45f
#define MAXWH 4096.0f
#define NEGF  -1e30f

#define GBOX 192
#define PTHREADS 192
#define TILE_BYTES (GBOX * CC * 4)     // 65280, multiple of 16

typedef unsigned long long u64;

// Global scratch (zero-initialized at load; g_hist reset by k_nms each run)
__device__ float  g_score[BB * NN];
__device__ float4 g_box[BB * NN];
__device__ int    g_cls[BB * NN];
__device__ int    g_hist[BB * BINS];
__device__ u64    g_bucket[BB * BINS * SLOTCAP];

__device__ __forceinline__ int score_bin(float s) {
    int bin = (int)((s - CONF_T) * (BINS / 0.75f));
    return min(max(bin, 0), BINS - 1);
}

// Decide fl(inter/denom) > IOU_T without division (exact vs reference).
__device__ __forceinline__ bool iou_sup(float inter, float denom) {
    float s = fmaf(-IOU_T, denom, inter);
    if (fabsf(s) > 1e-6f * denom) return s > 0.0f;
    return (inter / denom) > IOU_T;
}

__device__ __forceinline__ unsigned smem_addr(const void* p) {
    unsigned a;
    asm("{ .reg .u64 t; cvta.to.shared.u64 t, %1; cvt.u32.u64 %0, t; }"
        : "=r"(a) : "l"(p));
    return a;
}

// TMA-streamed prep: one cp.async.bulk per block (contiguous 65280B tile),
// then thread-per-box conf/argmax/box + bucket scatter.  (R9-identical.)
__global__ __launch_bounds__(PTHREADS) void k_prep(const float* __restrict__ pred) {
    extern __shared__ __align__(128) float sbuf[];
    __shared__ __align__(8) unsigned long long mbar;
    int tid = threadIdx.x;
    const float* src = pred + (long long)blockIdx.x * (GBOX * CC);
    unsigned sb = smem_addr(sbuf);
    unsigned mb = smem_addr(&mbar);

    if (tid == 0)
        asm volatile("mbarrier.init.shared.b64 [%0], %1;" :: "r"(mb), "r"(1) : "memory");
    __syncthreads();
    if (tid == 0) {
        asm volatile("mbarrier.arrive.expect_tx.shared.b64 _, [%0], %1;"
                     :: "r"(mb), "r"((unsigned)TILE_BYTES) : "memory");
        asm volatile("cp.async.bulk.shared::cluster.global.mbarrier::complete_tx::bytes "
                     "[%0], [%1], %2, [%3];"
                     :: "r"(sb), "l"(src), "r"((unsigned)TILE_BYTES), "r"(mb) : "memory");
    }
    {
        unsigned done = 0;
        while (!done) {
            asm volatile(
                "{\n\t.reg .pred p;\n\t"
                "mbarrier.try_wait.parity.acquire.cta.shared::cta.b64 p, [%1], %2, 0x989680;\n\t"
                "selp.b32 %0, 1, 0, p;\n\t}"
                : "=r"(done) : "r"(mb), "r"(0u) : "memory");
        }
    }

    {
        const float* p = sbuf + tid * CC;
        int w = blockIdx.x * GBOX + tid;
        float obj = p[4];
        if (obj <= CONF_T) { g_score[w] = NEGF; return; }

        float best = -1.0f;
        int   bj   = 0;
        #pragma unroll 8
        for (int c = 0; c < NCLS; c++) {
            float v = p[5 + c] * obj;            // same op order as reference
            if (v > best) { best = v; bj = c; }  // strict > == first-max argmax
        }
        bool valid = best > CONF_T;
        g_score[w] = valid ? best : NEGF;
        if (valid) {
            float x = p[0], y = p[1], ww = p[2], hh = p[3];
            g_box[w] = make_float4(x - ww * 0.5f, y - hh * 0.5f,
                                   x + ww * 0.5f, y + hh * 0.5f);
            g_cls[w] = bj;
            int b = w / NN;
            int n = w - b * NN;
            int cell = b * BINS + score_bin(best);
            int slot = atomicAdd(&g_hist[cell], 1);
            if (slot < SLOTCAP)
                g_bucket[cell * SLOTCAP + slot] =
                    ((u64)__float_as_uint(best) << 32) |
                    (unsigned)~(((unsigned)n << 7) | (unsigned)bj);
        }
    }
}

// Bitonic compare-exchange via shfl_xor (u64 key, descending)
__device__ __forceinline__ u64 cex_shfl(u64 key, int j, int k, int tid) {
    u64 other = __shfl_xor_sync(0xffffffffu, key, j);
    bool lower = (tid & j) == 0;
    bool desc  = (tid & k) == 0;
    bool takemax = (lower == desc);
    bool gt = key > other;
    return (takemax == gt) ? key : other;
}

// smem offsets (bytes)
#define OFF_KEYS   0                       // u64 [SORTN]        4096
#define OFF_CBOX   4096                    // float4 [CAP]       6144
#define OFF_CAREA  10240                   // float  [CAP]       1536
#define OFF_CARRY  11776                   // float4 [304]       4864
#define OFF_CARA   16640                   // float  [304]       1216
#define OFF_HIST   17856                   // int [BINS]         8192
#define OFF_MSKT   26048                   // u64 [CAP*CWORDS]  18432
#define OFF_PRES   44480                   // u64 [CWORDS]         64
#define OFF_KW     44544                   // u64 [CWORDS]         64
#define OFF_CCLS   44608                   // int [CAP]          1536
#define OFF_BOFF   46144                   // int [BINS]         8192
#define OFF_CLIST  54336                   // u16 [80*48]        7680
#define OFF_CLCNT  62016                   // int [80]            320
#define SMEM_TOTAL 62336

__global__ __launch_bounds__(1024, 1) void k_nms(float* __restrict__ out, int out_size) {
    extern __shared__ char smem[];
    u64*    keys  = (u64*)   (smem + OFF_KEYS);
    float4* cbox  = (float4*)(smem + OFF_CBOX);
    float*  carea = (float*) (smem + OFF_CAREA);
    float4* carry = (float4*)(smem + OFF_CARRY);
    float*  cara  = (float*) (smem + OFF_CARA);
    int*    hist  = (int*)   (smem + OFF_HIST);
    u64*    mskT  = (u64*)   (smem + OFF_MSKT);
    u64*    presw = (u64*)   (smem + OFF_PRES);
    u64*    kw    = (u64*)   (smem + OFF_KW);
    int*    ccls  = (int*)   (smem + OFF_CCLS);
    int*    boff  = (int*)   (smem + OFF_BOFF);
    unsigned short* clist = (unsigned short*)(smem + OFF_CLIST);
    int*    clcnt = (int*)   (smem + OFF_CLCNT);

    __shared__ int s_T, s_top, s_base, s_len, s_ovf, s_clovf, s_changed;
    __shared__ int s_tstar, s_c0, s_wstart, s_ocnt;
    __shared__ int s_wsum[32];
    __shared__ unsigned s_bal[32];

    int b = blockIdx.x, tid = threadIdx.x;
    const int bs = 1024;
    int lane = tid & 31;
    int wid  = tid >> 5;
    const float*  sc  = g_score + b * NN;
    const float4* bxp = g_box   + b * NN;
    const int*    clp = g_cls   + b * NN;

    for (int i = tid; i < BINS; i += bs) hist[i] = g_hist[b * BINS + i];
    if (tid == 0) { s_top = BINS - 1; s_base = 0; }
    __syncthreads();

    while (true) {
        // ── Windowed threshold selection (cap cum at CAP) ──
        if (tid == 0) { s_c0 = 0; s_wstart = s_top; s_T = -1; s_len = 0; s_ovf = 0; }
        __syncthreads();
        while (s_T < 0) {
            int wstart = s_wstart, c0 = s_c0;
            int bin = wstart - tid;
            int val = (bin >= 0) ? hist[bin] : 0;
            int incl = val;
            #pragma unroll
            for (int o = 1; o < 32; o <<= 1) {
                int y = __shfl_up_sync(0xffffffffu, incl, o);
                if (lane >= o) incl += y;
            }
            if (lane == 31) s_wsum[wid] = incl;
            __syncthreads();
            if (wid == 0) {
                int v = s_wsum[lane];
                #pragma unroll
                for (int o = 1; o < 32; o <<= 1) {
                    int y = __shfl_up_sync(0xffffffffu, v, o);
                    if (lane >= o) v += y;
                }
                s_wsum[lane] = v;
            }
            if (tid == 0) s_tstar = 1024;
            __syncthreads();
            if (wid > 0) incl += s_wsum[wid - 1];
            int cumBefore = c0 + incl - val;
            bool brk = (cumBefore > 0) && (c0 + incl > CAP);
            if (brk) atomicMin(&s_tstar, tid);
            __syncthreads();
            int tstar = s_tstar;
            if (tid < tstar && bin >= 0) boff[bin] = cumBefore;
            if (tstar < 1024) {
                if (tstar == 0) { if (tid == 0) { s_T = wstart + 1; s_len = c0; } }
                else if (tid == tstar - 1) { s_T = wstart - tstar + 1; s_len = c0 + incl; }
            } else if (wstart - 1023 <= 0) {
                if (bin == 0) { s_T = 0; s_len = c0 + incl; }
            } else {
                if (tid == 1023) s_c0 = c0 + incl;
                if (tid == 0)    s_wstart = wstart - 1024;
            }
            __syncthreads();
        }
        int T = s_T, top = s_top;
        int len = min(s_len, CAP);

        // ── Bucket copy + per-bin warp sort (global order = desc bins) ──
        for (int bin = top - wid; bin >= T; bin -= 32) {
            int cnt = hist[bin];
            if (cnt == 0) continue;
            if (cnt > SLOTCAP) { s_ovf = 1; continue; }
            u64 bk = (lane < cnt) ? g_bucket[(b * BINS + bin) * SLOTCAP + lane] : 0ULL;
            #pragma unroll
            for (int kk = 2; kk <= 32; kk <<= 1)
                for (int jj = kk >> 1; jj > 0; jj >>= 1)
                    bk = cex_shfl(bk, jj, kk, lane);
            if (lane < cnt) {
                int pos = boff[bin] + lane;
                if (pos < CAP) keys[pos] = bk;
            }
        }
        __syncthreads();

        // Rare fallback: bucket overflow -> scan-gather + full smem bitonic
        // (sort width SORTN=512, power of two; only first len<=CAP used after)
        if (s_ovf) {
            if (tid == 0) s_ocnt = 0;
            __syncthreads();
            const int NPAD = ((NN + bs - 1) / bs) * bs;
            for (int i = tid; i < NPAD; i += bs) {
                bool take = false;
                float s = NEGF;
                if (i < NN) {
                    s = sc[i];
                    if (s > CONF_T) {
                        int bin = score_bin(s);
                        take = (bin >= T && bin <= top);
                    }
                }
                unsigned bal = __ballot_sync(0xffffffffu, take);
                if (bal) {
                    int base;
                    if (lane == 0) base = atomicAdd(&s_ocnt, __popc(bal));
                    base = __shfl_sync(0xffffffffu, base, 0);
                    if (take) {
                        int pos = base + __popc(bal & ((1u << lane) - 1u));
                        if (pos < CAP)
                            keys[pos] = ((u64)__float_as_uint(s) << 32) |
                                        (unsigned)~(((unsigned)i << 7) |
                                                    (unsigned)clp[i]);
                    }
                }
            }
            __syncthreads();
            for (int i = len + tid; i < SORTN; i += bs) keys[i] = 0ULL;
            __syncthreads();
            for (int kk = 2; kk <= SORTN; kk <<= 1) {
                for (int jj = kk >> 1; jj > 0; jj >>= 1) {
                    if (tid < SORTN) {
                        int i = tid, ixj = i ^ jj;
                        if (ixj > i) {
                            u64 a = keys[i], c2 = keys[ixj];
                            bool sw = ((i & kk) == 0) ? (a < c2) : (a > c2);
                            if (sw) { keys[i] = c2; keys[ixj] = a; }
                        }
                    }
                    __syncthreads();
                }
            }
        }

        // ── Stage payloads ──
        u64 key = 0; int myidx = 0, mycls = 0;
        if (tid < len) {
            key = keys[tid];
            unsigned packed = ~(unsigned)key;
            myidx = (int)(packed >> 7);
            mycls = (int)(packed & 127u);
            float4 bx = bxp[myidx];
            float off = (float)mycls * MAXWH;
            float4 cb = make_float4(bx.x + off, bx.y + off, bx.z + off, bx.w + off);
            cbox[tid]  = cb;
            carea[tid] = (cb.z - cb.x) * (cb.w - cb.y);
            ccls[tid]  = mycls;
        }
        for (int t = tid; t < CAP * CWORDS; t += bs) mskT[t] = 0ULL;
        if (tid < CWORDS) presw[tid] = 0ULL;
        for (int i = tid; i < NCLS; i += bs) clcnt[i] = 0;
        if (tid == 0) s_clovf = 0;
        __syncthreads();

        if (tid < len) {
            int slot = atomicAdd(&clcnt[mycls], 1);
            if (slot < CLSCAP) clist[mycls * CLSCAP + slot] = (unsigned short)tid;
            else s_clovf = 1;
        }

        if (s_base > 0 && tid < len) {
            float4 bi = cbox[tid];
            float  ai = carea[tid];
            bool sup = false;
            for (int q = 0; q < s_base && !sup; q++) {
                float4 kb = carry[q];
                float xx1 = fmaxf(bi.x, kb.x), yy1 = fmaxf(bi.y, kb.y);
                float xx2 = fminf(bi.z, kb.z), yy2 = fminf(bi.w, kb.w);
                float inter = fmaxf(xx2 - xx1, 0.0f) * fmaxf(yy2 - yy1, 0.0f);
                if (inter > 0.0f)
                    sup = iou_sup(inter, ai + cara[q] - inter);
            }
            if (sup) atomicOr(&presw[tid >> 6], 1ULL << (tid & 63));
        }
        __syncthreads();

        // ── Column-major suppression mask via class lists ──
        if (!s_clovf) {
            if (tid < len) {
                int c = tid;
                float4 bi = cbox[c];
                float  ai = carea[c];
                int cnt = clcnt[mycls];
                for (int q = 0; q < cnt; q++) {
                    int j = clist[mycls * CLSCAP + q];
                    if (j < c) {
                        float4 bj = cbox[j];
                        float xx1 = fmaxf(bi.x, bj.x), yy1 = fmaxf(bi.y, bj.y);
                        float xx2 = fminf(bi.z, bj.z), yy2 = fminf(bi.w, bj.w);
                        float inter = fmaxf(xx2 - xx1, 0.0f) * fmaxf(yy2 - yy1, 0.0f);
                        if (inter > 0.0f && iou_sup(inter, ai + carea[j] - inter))
                            mskT[c * CWORDS + (j >> 6)] |= 1ULL << (j & 63);
                    }
                }
            }
        } else {
            for (int t = tid; t < CAP * CWORDS; t += bs) {
                int c = t / CWORDS, w = t - c * CWORDS;
                u64 mword = 0ULL;
                if (c < len) {
                    float4 bi = cbox[c];
                    float  ai = carea[c];
                    int ci = ccls[c];
                    int jbeg = w << 6;
                    int jend = min(jbeg + 64, c);
                    for (int j = jbeg; j < jend; j++) {
                        if (ccls[j] != ci) continue;
                        float4 bj = cbox[j];
                        float xx1 = fmaxf(bi.x, bj.x), yy1 = fmaxf(bi.y, bj.y);
                        float xx2 = fminf(bi.z, bj.z), yy2 = fminf(bi.w, bj.w);
                        float inter = fmaxf(xx2 - xx1, 0.0f) * fmaxf(yy2 - yy1, 0.0f);
                        if (inter > 0.0f && iou_sup(inter, ai + carea[j] - inter))
                            mword |= 1ULL << (j & 63);
                    }
                }
                mskT[t] = mword;
            }
        }
        __syncthreads();

        // ── Exact greedy via antitone fixpoint iteration ──
        bool presb = false;
        if (tid < CAP) presb = (presw[tid >> 6] >> (tid & 63)) & 1ULL;
        bool keptf = (tid < len) && !presb;
        unsigned balv = __ballot_sync(0xffffffffu, keptf);
        if (lane == 0) s_bal[wid] = balv;
        if (tid == 0) s_changed = 0;
        __syncthreads();
        if (tid < CWORDS) kw[tid] = (u64)s_bal[2 * tid] | ((u64)s_bal[2 * tid + 1] << 32);
        __syncthreads();
        for (int pass = 0; pass <= CAP; pass++) {
            bool sup = false;
            if (tid < len) {
                const u64* row = mskT + tid * CWORDS;
                u64 acc = 0ULL;
                #pragma unroll
                for (int w = 0; w < CWORDS; w++) acc |= kw[w] & row[w];
                sup = acc != 0ULL;
            }
            bool nk = (tid < len) && !presb && !sup;
            __syncthreads();
            unsigned nb = __ballot_sync(0xffffffffu, nk);
            if (lane == 0) s_bal[wid] = nb;
            __syncthreads();
            if (tid < CWORDS) {
                u64 nw = (u64)s_bal[2 * tid] | ((u64)s_bal[2 * tid + 1] << 32);
                if (nw != kw[tid]) s_changed = 1;
                kw[tid] = nw;
            }
            __syncthreads();
            if (!s_changed) break;
            if (tid == 0) s_changed = 0;
            __syncthreads();
        }

        // ── Compaction + ordered output ──
        bool kept = false;
        if (tid < CAP) kept = (kw[tid >> 6] >> (tid & 63)) & 1ULL;
        int flag = (tid < len && kept) ? 1 : 0;
        unsigned bal = __ballot_sync(0xffffffffu, flag);
        int ex = __popc(bal & ((1u << lane) - 1u));
        if (lane == 0) s_wsum[wid] = __popc(bal);
        __syncthreads();
        if (tid < 16) {
            int v = s_wsum[tid];
            #pragma unroll
            for (int o = 1; o < 16; o <<= 1) {
                int y = __shfl_up_sync(0x0000ffffu, v, o);
                if (tid >= o) v += y;
            }
            s_wsum[tid] = v;
        }
        __syncthreads();
        int total = s_wsum[15];
        int basep = s_base;
        bool cont = (basep + total < MAXDET) && (s_T > 0);

        if (flag) {
            int warpbase = (tid >= 32) ? s_wsum[wid - 1] : 0;
            int pos = basep + warpbase + ex;
            if (pos < MAXDET) {
                float4 bx = bxp[myidx];
                int base = b * MAXDET * 6 + pos * 6;
                if (base + 5 < out_size) {
                    out[base + 0] = bx.x;
                    out[base + 1] = bx.y;
                    out[base + 2] = bx.z;
                    out[base + 3] = bx.w;
                    out[base + 4] = __uint_as_float((unsigned)(key >> 32));
                    out[base + 5] = (float)mycls;
                }
                int ko = BB * MAXDET * 6 + b * MAXDET + pos;
                if (ko < out_size) out[ko] = 1.0f;
                if (cont) { carry[pos] = cbox[tid]; cara[pos] = carea[tid]; }
            }
        }
        __syncthreads();
        if (tid == 0) { s_base = basep + total; s_top = s_T - 1; }
        __syncthreads();
        if (!cont) break;
    }

    // Zero-pad remaining rows + keeps
    int fin = min(s_base, MAXDET);
    for (int k2 = fin + tid; k2 < MAXDET; k2 += bs) {
        int base = b * MAXDET * 6 + k2 * 6;
        #pragma unroll
        for (int c2 = 0; c2 < 6; c2++)
            if (base + c2 < out_size) out[base + c2] = 0.0f;
        int ko = BB * MAXDET * 6 + b * MAXDET + k2;
        if (ko < out_size) out[ko] = 0.0f;
    }

    // Reset histogram for next graph replay
    for (int i = tid; i < BINS; i += bs) g_hist[b * BINS + i] = 0;
}

extern "C" void kernel_launch(void* const* d_in, const int* in_sizes, int n_in,
                              void* d_out, int out_size) {
    const float* pred = (const float*)d_in[0];
    float* out = (float*)d_out;

    cudaFuncSetAttribute(k_prep, cudaFuncAttributeMaxDynamicSharedMemorySize, TILE_BYTES);
    int blocks = (BB * NN) / GBOX;   // 2100
    k_prep<<<blocks, PTHREADS, TILE_BYTES>>>(pred);

    cudaFuncSetAttribute(k_nms, cudaFuncAttributeMaxDynamicSharedMemorySize, SMEM_TOTAL);
    k_nms<<<BB, 1024, SMEM_TOTAL>>>(out, out_size);
}